// round 13
// baseline (speedup 1.0000x reference)
#include <cuda_runtime.h>
#include <cuda_fp16.h>
#include <cstdint>

// ---------------------------------------------------------------------------
// DeepFM forward — R13:
//   GEMM1: single-fp16 HMMA, TM=64 tile, k64, 2-stage double buffer,
//          3 CTAs/SM (launch_bounds(256,3)), fused column stats.
//   GEMM2: single fp16, TM=64, 2-stage, BN+ReLU fused in A path (R12, proven).
//   4 launches: pre, gemm1, gemm2, final.
//   B=16384, F=26, D=32, DIN=832, H1=256, H2=128, V=100000
// ---------------------------------------------------------------------------

#define BATCH  16384
#define NF     26
#define ED     32
#define DIN    832
#define H1N    256
#define H2N    128
#define VOCAB  100000
#define BN_EPS 1e-5f

// ---- scratch ---------------------------------------------------------------
__device__ unsigned short g_Xh[(size_t)BATCH * DIN];     // fp16 X
__device__ float          g_H1[(size_t)BATCH * H1N];
__device__ float          g_H2[(size_t)BATCH * H2N];
__device__ unsigned short g_W1T[H1N * DIN];              // fp16 W1^T
__device__ unsigned short g_W2T[H2N * H1N];              // fp16 W2^T
__device__ float g_fm[BATCH];
__device__ float g_stats1[2 * H1N];
__device__ float g_stats2[2 * H2N];

// ---- PTX helpers -----------------------------------------------------------
__device__ __forceinline__ uint32_t smem_u32(const void* p) {
    uint32_t a;
    asm("{ .reg .u64 t; cvta.to.shared.u64 t, %1; cvt.u32.u64 %0, t; }"
        : "=r"(a) : "l"(p));
    return a;
}
__device__ __forceinline__ void cp16(uint32_t dst, const void* src) {
    asm volatile("cp.async.cg.shared.global [%0], [%1], 16;"
                 :: "r"(dst), "l"(src));
}
#define CP_COMMIT() asm volatile("cp.async.commit_group;" ::: "memory")

__device__ __forceinline__ void ldsm4(uint32_t* r, uint32_t addr) {
    asm volatile("ldmatrix.sync.aligned.m8n8.x4.shared.b16 {%0,%1,%2,%3}, [%4];"
                 : "=r"(r[0]), "=r"(r[1]), "=r"(r[2]), "=r"(r[3]) : "r"(addr));
}
__device__ __forceinline__ void mma16816(float* d, const uint32_t* a,
                                         const uint32_t* b) {
    asm volatile(
        "mma.sync.aligned.m16n8k16.row.col.f32.f16.f16.f32 "
        "{%0,%1,%2,%3}, {%4,%5,%6,%7}, {%8,%9}, {%0,%1,%2,%3};"
        : "+f"(d[0]), "+f"(d[1]), "+f"(d[2]), "+f"(d[3])
        : "r"(a[0]), "r"(a[1]), "r"(a[2]), "r"(a[3]), "r"(b[0]), "r"(b[1]));
}

// ---- fused pre kernel: zero stats | prep W | gather+FM ---------------------
__global__ void pre_k(const int* __restrict__ xc,
                      const float* __restrict__ lin_tab,
                      const float* __restrict__ lat_tab,
                      const float* __restrict__ bias,
                      const float* __restrict__ W1,
                      const float* __restrict__ W2) {
    const int blk = blockIdx.x;
    const int tid = threadIdx.x;

    if (blk < 2048) {                       // ---- gather + FM ----
        int row  = blk * 8 + (tid >> 5);
        int lane = tid & 31;
        int   idx  = 0;
        float linv = 0.f;
        if (lane < NF) {
            idx  = xc[row * NF + lane];
            linv = lin_tab[lane * VOCAB + idx];
        }
        float sdim = 0.f, sq = 0.f;
        unsigned short* xh = &g_Xh[(size_t)row * DIN];
#pragma unroll
        for (int f = 0; f < NF; ++f) {
            int id = __shfl_sync(0xffffffffu, idx, f);
            float e = lat_tab[((size_t)f * VOCAB + id) * ED + lane];
            xh[f * ED + lane] = __half_as_ushort(__float2half(e));
            sdim += e; sq += e * e;
        }
        float t = sdim * sdim - sq;
#pragma unroll
        for (int o = 16; o; o >>= 1) {
            t    += __shfl_xor_sync(0xffffffffu, t, o);
            linv += __shfl_xor_sync(0xffffffffu, linv, o);
        }
        if (lane == 0) g_fm[row] = linv + 0.5f * t + bias[0];
    } else if (blk < 2528) {                // ---- weight prep ----
        const int t1 = DIN * H1N;
        const int tot = t1 + H1N * H2N;
        for (int i = (blk - 2048) * 256 + tid; i < tot; i += 480 * 256) {
            if (i < t1) {
                int k = i / H1N, n = i % H1N;
                g_W1T[n * DIN + k] = __half_as_ushort(__float2half(W1[i]));
            } else {
                int j = i - t1;
                int k = j / H2N, n = j % H2N;
                g_W2T[n * H1N + k] = __half_as_ushort(__float2half(W2[j]));
            }
        }
    } else {                                // ---- zero stats ----
        g_stats1[tid] = 0.f; g_stats1[H1N + tid] = 0.f;
        if (tid < H2N) { g_stats2[tid] = 0.f; g_stats2[H2N + tid] = 0.f; }
    }
}

// ---- GEMM1: single fp16, TM=64, 2-stage double buffer, 3 CTAs/SM -----------
// C[B x 256] = A[B x 832] @ Bt[256 x 832]^T + bias; grid (B/64, 2).
// 8 warps: 4 m-warps x 16 rows, 2 n-warps x 64 cols.
template<int KTOT, int NCOLS>
__global__ __launch_bounds__(256, 3)
void gemm_fp16(const unsigned short* __restrict__ A,
               const unsigned short* __restrict__ Bt,
               const float* __restrict__ bias, float* __restrict__ C,
               float* __restrict__ stats) {
    extern __shared__ char smem[];
    constexpr int STR    = 72;
    constexpr int TILE_A = 64 * STR * 2;         // 9216 B
    constexpr int TILE_B = 128 * STR * 2;        // 18432 B
    constexpr int STAGE  = TILE_A + TILE_B;      // 27648 B
    constexpr int NCHUNK = KTOT / 64;
    __shared__ float csum[128], csq[128];

    const uint32_t sb = smem_u32(smem);
    const int tid = threadIdx.x;
    const int lane = tid & 31;
    const int wid = tid >> 5;
    const int warp_m = wid & 3;
    const int warp_n = wid >> 2;
    const int rowBase = blockIdx.x * 64;
    const int colBase = blockIdx.y * 128;

    float acc[8][4];
#pragma unroll
    for (int j = 0; j < 8; ++j)
#pragma unroll
        for (int k = 0; k < 4; ++k) acc[j][k] = 0.f;

    const int a_row = warp_m * 16 + (lane & 15);
    const int a_col8 = (lane >> 4) << 3;
    const int b_row_base = warp_n * 64 + (lane & 7) + ((lane >> 4) << 3);
    const int b_col8 = ((lane >> 3) & 1) << 3;

    auto load_stage = [&](int kc) {
        const uint32_t base = sb + (kc & 1) * STAGE;
        // A: 64 rows x 8 segs = 512 cp16
#pragma unroll
        for (int i = tid; i < 64 * 8; i += 256) {
            int row = i >> 3, seg = i & 7;
            uint32_t soff = (uint32_t)(row * STR + seg * 8) * 2;
            size_t ga = (size_t)(rowBase + row) * KTOT + kc * 64 + seg * 8;
            cp16(base + soff, A + ga);
        }
        // B: 128 rows x 8 segs = 1024 cp16
#pragma unroll
        for (int i = tid; i < 128 * 8; i += 256) {
            int row = i >> 3, seg = i & 7;
            uint32_t soff = (uint32_t)(row * STR + seg * 8) * 2;
            size_t gb = (size_t)(colBase + row) * KTOT + kc * 64 + seg * 8;
            cp16(base + TILE_A + soff, Bt + gb);
        }
        CP_COMMIT();
    };

    load_stage(0);

    for (int kc = 0; kc < NCHUNK; ++kc) {
        if (kc + 1 < NCHUNK) {
            load_stage(kc + 1);
            asm volatile("cp.async.wait_group 1;" ::: "memory");
        } else {
            asm volatile("cp.async.wait_group 0;" ::: "memory");
        }
        __syncthreads();

        const uint32_t baseA = sb + (kc & 1) * STAGE;
        const uint32_t baseB = baseA + TILE_A;
#pragma unroll
        for (int ks = 0; ks < 4; ++ks) {
            uint32_t ah[4];
            ldsm4(ah, baseA + (uint32_t)(a_row * STR + ks * 16 + a_col8) * 2);
#pragma unroll
            for (int nb = 0; nb < 4; ++nb) {
                uint32_t bh[4];
                uint32_t off = (uint32_t)((b_row_base + nb * 16) * STR +
                                          ks * 16 + b_col8) * 2;
                ldsm4(bh, baseB + off);
                mma16816(acc[2 * nb],     ah, bh);
                mma16816(acc[2 * nb + 1], ah, bh + 2);
            }
        }
        __syncthreads();
    }

    // epilogue: bias add, store, fused column stats
    if (tid < 128) { csum[tid] = 0.f; csq[tid] = 0.f; }
    __syncthreads();
#pragma unroll
    for (int nt = 0; nt < 8; ++nt) {
        int cl = warp_n * 64 + nt * 8 + 2 * (lane & 3);
        int c  = colBase + cl;
        float2 bv = *(const float2*)&bias[c];
        int r0 = rowBase + warp_m * 16 + (lane >> 2);
        float2 v0 = {acc[nt][0] + bv.x, acc[nt][1] + bv.y};
        float2 v1 = {acc[nt][2] + bv.x, acc[nt][3] + bv.y};
        *(float2*)&C[(size_t)r0 * NCOLS + c]       = v0;
        *(float2*)&C[(size_t)(r0 + 8) * NCOLS + c] = v1;
        atomicAdd(&csum[cl],     v0.x + v1.x);
        atomicAdd(&csum[cl + 1], v0.y + v1.y);
        atomicAdd(&csq[cl],      v0.x * v0.x + v1.x * v1.x);
        atomicAdd(&csq[cl + 1],  v0.y * v0.y + v1.y * v1.y);
    }
    __syncthreads();
    if (tid < 128) {
        atomicAdd(&stats[colBase + tid],         csum[tid]);
        atomicAdd(&stats[NCOLS + colBase + tid], csq[tid]);
    }
}

// ---- GEMM2: single fp16, TM=64, 2-stage, act fused, stats (R12, proven) ----
__global__ __launch_bounds__(256, 2)
void gemm2_k(const float* __restrict__ H1,
             const unsigned short* __restrict__ Bt,
             const float* __restrict__ g1, const float* __restrict__ be1,
             const float* __restrict__ bias, float* __restrict__ C,
             float* __restrict__ stats) {
    extern __shared__ char smem[];
    constexpr int KTOT = H1N, NCOLS = H2N;
    constexpr int STR    = 72;
    constexpr int TILE_A = 64 * STR * 2;
    constexpr int TILE_B = 128 * STR * 2;
    constexpr int STAGE  = TILE_A + TILE_B;
    constexpr int NCHUNK = KTOT / 64;            // 4
    __shared__ float sc[H1N], sh[H1N];
    __shared__ float csum[128], csq[128];

    const uint32_t sb = smem_u32(smem);
    const int tid = threadIdx.x;
    const int lane = tid & 31;
    const int wid = tid >> 5;
    const int warp_m = wid & 3;
    const int warp_n = wid >> 2;
    const int rowBase = blockIdx.x * 64;

    {
        float s  = g_stats1[tid];
        float sq = g_stats1[H1N + tid];
        float mean = s * (1.f / BATCH);
        float var  = sq * (1.f / BATCH) - mean * mean;
        float rstd = rsqrtf(var + BN_EPS);
        float scl  = g1[tid] * rstd;
        sc[tid] = scl;
        sh[tid] = be1[tid] - mean * scl;
    }
    __syncthreads();

    float acc[8][4];
#pragma unroll
    for (int j = 0; j < 8; ++j)
#pragma unroll
        for (int k = 0; k < 4; ++k) acc[j][k] = 0.f;

    const int a_row = warp_m * 16 + (lane & 15);
    const int a_col8 = (lane >> 4) << 3;
    const int b_row_base = warp_n * 64 + (lane & 7) + ((lane >> 4) << 3);
    const int b_col8 = ((lane >> 3) & 1) << 3;

    const int al_row = tid >> 2;
    const int al_seg = tid & 3;

    float4 ra[4];
    auto ldg_A = [&](int kc) {
#pragma unroll
        for (int p = 0; p < 4; ++p) {
            int kk = kc * 64 + (al_seg + p * 4) * 4;
            ra[p] = *(const float4*)&H1[(size_t)(rowBase + al_row) * KTOT + kk];
        }
    };
    auto store_A = [&](int kc) {
        const uint32_t base = (kc & 1) * STAGE;
#pragma unroll
        for (int p = 0; p < 4; ++p) {
            int kk = kc * 64 + (al_seg + p * 4) * 4;
            int cl = kk & (H1N - 1);
            float h0 = fmaxf(fmaf(ra[p].x, sc[cl + 0], sh[cl + 0]), 0.f);
            float h1 = fmaxf(fmaf(ra[p].y, sc[cl + 1], sh[cl + 1]), 0.f);
            float h2 = fmaxf(fmaf(ra[p].z, sc[cl + 2], sh[cl + 2]), 0.f);
            float h3 = fmaxf(fmaf(ra[p].w, sc[cl + 3], sh[cl + 3]), 0.f);
            __half2 a = __floats2half2_rn(h0, h1);
            __half2 b = __floats2half2_rn(h2, h3);
            uint32_t soff = base +
                (uint32_t)(al_row * STR + (al_seg + p * 4) * 4) * 2;
            *(uint32_t*)(smem + soff)     = *(uint32_t*)&a;
            *(uint32_t*)(smem + soff + 4) = *(uint32_t*)&b;
        }
    };
    auto load_B = [&](int kc) {
        const uint32_t base = sb + (kc & 1) * STAGE + TILE_A;
#pragma unroll
        for (int i = tid; i < 128 * 8; i += 256) {
            int row = i >> 3, seg = i & 7;
            uint32_t soff = (uint32_t)(row * STR + seg * 8) * 2;
            size_t gb = (size_t)row * KTOT + kc * 64 + seg * 8;
            cp16(base + soff, Bt + gb);
        }
        CP_COMMIT();
    };

    ldg_A(0);
    load_B(0);
    store_A(0);
    ldg_A(1);

    for (int kc = 0; kc < NCHUNK; ++kc) {
        if (kc + 1 < NCHUNK) {
            load_B(kc + 1);
            store_A(kc + 1);
            if (kc + 2 < NCHUNK) ldg_A(kc + 2);
            asm volatile("cp.async.wait_group 1;" ::: "memory");
        } else {
            asm volatile("cp.async.wait_group 0;" ::: "memory");
        }
        __syncthreads();

        const uint32_t baseA = sb + (kc & 1) * STAGE;
        const uint32_t baseB = baseA + TILE_A;
#pragma unroll
        for (int ks = 0; ks < 4; ++ks) {
            uint32_t ah[4];
            ldsm4(ah, baseA + (uint32_t)(a_row * STR + ks * 16 + a_col8) * 2);
#pragma unroll
            for (int nb = 0; nb < 4; ++nb) {
                uint32_t bh[4];
                uint32_t off = (uint32_t)((b_row_base + nb * 16) * STR +
                                          ks * 16 + b_col8) * 2;
                ldsm4(bh, baseB + off);
                mma16816(acc[2 * nb],     ah, bh);
                mma16816(acc[2 * nb + 1], ah, bh + 2);
            }
        }
        __syncthreads();
    }

    if (tid < 128) { csum[tid] = 0.f; csq[tid] = 0.f; }
    __syncthreads();
#pragma unroll
    for (int nt = 0; nt < 8; ++nt) {
        int cl = warp_n * 64 + nt * 8 + 2 * (lane & 3);
        float2 bv = *(const float2*)&bias[cl];
        int r0 = rowBase + warp_m * 16 + (lane >> 2);
        float2 v0 = {acc[nt][0] + bv.x, acc[nt][1] + bv.y};
        float2 v1 = {acc[nt][2] + bv.x, acc[nt][3] + bv.y};
        *(float2*)&C[(size_t)r0 * NCOLS + cl]       = v0;
        *(float2*)&C[(size_t)(r0 + 8) * NCOLS + cl] = v1;
        atomicAdd(&csum[cl],     v0.x + v1.x);
        atomicAdd(&csum[cl + 1], v0.y + v1.y);
        atomicAdd(&csq[cl],      v0.x * v0.x + v1.x * v1.x);
        atomicAdd(&csq[cl + 1],  v0.y * v0.y + v1.y * v1.y);
    }
    __syncthreads();
    if (tid < 128) {
        atomicAdd(&stats[tid],         csum[tid]);
        atomicAdd(&stats[NCOLS + tid], csq[tid]);
    }
}

// ---- final: out = fm + relu(BN(H2)) @ W3 + b3 ------------------------------
__global__ void final_k(const float* __restrict__ W3, const float* __restrict__ b3,
                        const float* __restrict__ g2, const float* __restrict__ be2,
                        float* __restrict__ out) {
    __shared__ float sc[H2N], sh[H2N], w3s[H2N];
    int tid = threadIdx.x;
    if (tid < H2N) {
        float s  = g_stats2[tid];
        float sq = g_stats2[H2N + tid];
        float mean = s * (1.f / BATCH);
        float var  = sq * (1.f / BATCH) - mean * mean;
        float rstd = rsqrtf(var + BN_EPS);
        float scl  = g2[tid] * rstd;
        sc[tid] = scl;
        sh[tid] = be2[tid] - mean * scl;
        w3s[tid] = W3[tid];
    }
    __syncthreads();
    int warp = tid >> 5, lane = tid & 31;
    int row = blockIdx.x * 8 + warp;
    float acc = 0.f;
#pragma unroll
    for (int j = 0; j < 4; ++j) {
        int c = lane + j * 32;
        float v = g_H2[(size_t)row * H2N + c];
        acc += fmaxf(fmaf(v, sc[c], sh[c]), 0.f) * w3s[c];
    }
#pragma unroll
    for (int o = 16; o; o >>= 1) acc += __shfl_xor_sync(0xffffffffu, acc, o);
    if (lane == 0) out[row] = g_fm[row] + acc + b3[0];
}

// ---------------------------------------------------------------------------
extern "C" void kernel_launch(void* const* d_in, const int* in_sizes, int n_in,
                              void* d_out, int out_size) {
    const int*   xc   = (const int*)  d_in[0];
    const float* lin  = (const float*)d_in[1];
    const float* lat  = (const float*)d_in[2];
    const float* W1   = (const float*)d_in[3];
    const float* b1   = (const float*)d_in[4];
    const float* g1   = (const float*)d_in[5];
    const float* be1  = (const float*)d_in[6];
    const float* W2   = (const float*)d_in[7];
    const float* b2   = (const float*)d_in[8];
    const float* g2   = (const float*)d_in[9];
    const float* be2  = (const float*)d_in[10];
    const float* W3   = (const float*)d_in[11];
    const float* b3   = (const float*)d_in[12];
    const float* bias = (const float*)d_in[13];
    float* out = (float*)d_out;

    unsigned short *pXh, *pW1, *pW2;
    float *pH1, *pH2, *pS1, *pS2;
    cudaGetSymbolAddress((void**)&pXh, g_Xh);
    cudaGetSymbolAddress((void**)&pW1, g_W1T);
    cudaGetSymbolAddress((void**)&pW2, g_W2T);
    cudaGetSymbolAddress((void**)&pH1, g_H1);
    cudaGetSymbolAddress((void**)&pH2, g_H2);
    cudaGetSymbolAddress((void**)&pS1, g_stats1);
    cudaGetSymbolAddress((void**)&pS2, g_stats2);

    constexpr int SMEM = 2 * (64 + 128) * 72 * 2;          // 55296 per CTA
    cudaFuncSetAttribute(gemm_fp16<DIN, H1N>,
                         cudaFuncAttributeMaxDynamicSharedMemorySize, SMEM);
    cudaFuncSetAttribute(gemm2_k,
                         cudaFuncAttributeMaxDynamicSharedMemorySize, SMEM);

    pre_k<<<2529, 256>>>(xc, lin, lat, bias, W1, W2);
    gemm_fp16<DIN, H1N><<<dim3(BATCH / 64, H1N / 128), 256, SMEM>>>(
        pXh, pW1, b1, pH1, pS1);
    gemm2_k<<<BATCH / 64, 256, SMEM>>>(pH1, pW2, g1, be1, b2, pH2, pS2);
    final_k<<<BATCH / 8, 256>>>(W3, b3, g2, be2, out);
}

// round 15
// speedup vs baseline: 1.2474x; 1.2474x over previous
#include <cuda_runtime.h>
#include <cuda_fp16.h>
#include <cstdint>

// ---------------------------------------------------------------------------
// DeepFM forward — R14 (= R12 + 3-stage gemm1 pipeline):
//   GEMM1: single-fp16 HMMA, TM=128, k64, THREE-stage cp.async pipeline
//          (two loads in flight), 2 CTAs/SM, fused column stats.
//   GEMM2: single fp16, TM=64, 2-stage, BN+ReLU fused in A path (R12, proven).
//   4 launches: pre, gemm1, gemm2, final.
//   B=16384, F=26, D=32, DIN=832, H1=256, H2=128, V=100000
// ---------------------------------------------------------------------------

#define BATCH  16384
#define NF     26
#define ED     32
#define DIN    832
#define H1N    256
#define H2N    128
#define VOCAB  100000
#define BN_EPS 1e-5f

// ---- scratch ---------------------------------------------------------------
__device__ unsigned short g_Xh[(size_t)BATCH * DIN];     // fp16 X
__device__ float          g_H1[(size_t)BATCH * H1N];
__device__ float          g_H2[(size_t)BATCH * H2N];
__device__ unsigned short g_W1T[H1N * DIN];              // fp16 W1^T
__device__ unsigned short g_W2T[H2N * H1N];              // fp16 W2^T
__device__ float g_fm[BATCH];
__device__ float g_stats1[2 * H1N];
__device__ float g_stats2[2 * H2N];

// ---- PTX helpers -----------------------------------------------------------
__device__ __forceinline__ uint32_t smem_u32(const void* p) {
    uint32_t a;
    asm("{ .reg .u64 t; cvta.to.shared.u64 t, %1; cvt.u32.u64 %0, t; }"
        : "=r"(a) : "l"(p));
    return a;
}
__device__ __forceinline__ void cp16(uint32_t dst, const void* src) {
    asm volatile("cp.async.cg.shared.global [%0], [%1], 16;"
                 :: "r"(dst), "l"(src));
}
#define CP_COMMIT() asm volatile("cp.async.commit_group;" ::: "memory")

__device__ __forceinline__ void ldsm4(uint32_t* r, uint32_t addr) {
    asm volatile("ldmatrix.sync.aligned.m8n8.x4.shared.b16 {%0,%1,%2,%3}, [%4];"
                 : "=r"(r[0]), "=r"(r[1]), "=r"(r[2]), "=r"(r[3]) : "r"(addr));
}
__device__ __forceinline__ void mma16816(float* d, const uint32_t* a,
                                         const uint32_t* b) {
    asm volatile(
        "mma.sync.aligned.m16n8k16.row.col.f32.f16.f16.f32 "
        "{%0,%1,%2,%3}, {%4,%5,%6,%7}, {%8,%9}, {%0,%1,%2,%3};"
        : "+f"(d[0]), "+f"(d[1]), "+f"(d[2]), "+f"(d[3])
        : "r"(a[0]), "r"(a[1]), "r"(a[2]), "r"(a[3]), "r"(b[0]), "r"(b[1]));
}

// ---- fused pre kernel: zero stats | prep W | gather+FM ---------------------
__global__ void pre_k(const int* __restrict__ xc,
                      const float* __restrict__ lin_tab,
                      const float* __restrict__ lat_tab,
                      const float* __restrict__ bias,
                      const float* __restrict__ W1,
                      const float* __restrict__ W2) {
    const int blk = blockIdx.x;
    const int tid = threadIdx.x;

    if (blk < 2048) {                       // ---- gather + FM ----
        int row  = blk * 8 + (tid >> 5);
        int lane = tid & 31;
        int   idx  = 0;
        float linv = 0.f;
        if (lane < NF) {
            idx  = xc[row * NF + lane];
            linv = lin_tab[lane * VOCAB + idx];
        }
        float sdim = 0.f, sq = 0.f;
        unsigned short* xh = &g_Xh[(size_t)row * DIN];
#pragma unroll
        for (int f = 0; f < NF; ++f) {
            int id = __shfl_sync(0xffffffffu, idx, f);
            float e = lat_tab[((size_t)f * VOCAB + id) * ED + lane];
            xh[f * ED + lane] = __half_as_ushort(__float2half(e));
            sdim += e; sq += e * e;
        }
        float t = sdim * sdim - sq;
#pragma unroll
        for (int o = 16; o; o >>= 1) {
            t    += __shfl_xor_sync(0xffffffffu, t, o);
            linv += __shfl_xor_sync(0xffffffffu, linv, o);
        }
        if (lane == 0) g_fm[row] = linv + 0.5f * t + bias[0];
    } else if (blk < 2528) {                // ---- weight prep ----
        const int t1 = DIN * H1N;
        const int tot = t1 + H1N * H2N;
        for (int i = (blk - 2048) * 256 + tid; i < tot; i += 480 * 256) {
            if (i < t1) {
                int k = i / H1N, n = i % H1N;
                g_W1T[n * DIN + k] = __half_as_ushort(__float2half(W1[i]));
            } else {
                int j = i - t1;
                int k = j / H2N, n = j % H2N;
                g_W2T[n * H1N + k] = __half_as_ushort(__float2half(W2[j]));
            }
        }
    } else {                                // ---- zero stats ----
        g_stats1[tid] = 0.f; g_stats1[H1N + tid] = 0.f;
        if (tid < H2N) { g_stats2[tid] = 0.f; g_stats2[H2N + tid] = 0.f; }
    }
}

// ---- GEMM1: single fp16, TM=128, 3-stage pipeline, fused stats -------------
template<int KTOT, int NCOLS>
__global__ __launch_bounds__(256, 2)
void gemm_fp16(const unsigned short* __restrict__ A,
               const unsigned short* __restrict__ Bt,
               const float* __restrict__ bias, float* __restrict__ C,
               float* __restrict__ stats) {
    extern __shared__ char smem[];
    constexpr int STR    = 72;
    constexpr int TILE   = 128 * STR * 2;      // 18432 B (one array)
    constexpr int STAGE  = 2 * TILE;           // A + B = 36864 B
    constexpr int NSTG   = 3;
    constexpr int NCHUNK = KTOT / 64;
    __shared__ float csum[128], csq[128];

    const uint32_t sb = smem_u32(smem);
    const int tid = threadIdx.x;
    const int lane = tid & 31;
    const int wid = tid >> 5;
    const int warp_m = wid & 3;
    const int warp_n = wid >> 2;
    const int rowBase = blockIdx.x * 128;
    const int colBase = blockIdx.y * 128;

    float acc[2][8][4];
#pragma unroll
    for (int i = 0; i < 2; ++i)
#pragma unroll
        for (int j = 0; j < 8; ++j)
#pragma unroll
            for (int k = 0; k < 4; ++k) acc[i][j][k] = 0.f;

    const int a_row = warp_m * 32 + (lane & 15);
    const int a_col8 = (lane >> 4) << 3;
    const int b_row_base = warp_n * 64 + (lane & 7) + ((lane >> 4) << 3);
    const int b_col8 = ((lane >> 3) & 1) << 3;

    auto load_stage = [&](int kc) {
        const uint32_t base = sb + (kc % NSTG) * STAGE;
#pragma unroll
        for (int i = tid; i < 128 * 8; i += 256) {
            int row = i >> 3, seg = i & 7;
            uint32_t soff = (uint32_t)(row * STR + seg * 8) * 2;
            size_t ga = (size_t)(rowBase + row) * KTOT + kc * 64 + seg * 8;
            size_t gb = (size_t)(colBase + row) * KTOT + kc * 64 + seg * 8;
            cp16(base + soff,        A + ga);
            cp16(base + TILE + soff, Bt + gb);
        }
        CP_COMMIT();
    };

    load_stage(0);
    if (NCHUNK > 1) load_stage(1);

    for (int kc = 0; kc < NCHUNK; ++kc) {
        if (kc + 2 < NCHUNK) {
            load_stage(kc + 2);
            asm volatile("cp.async.wait_group 2;" ::: "memory");
        } else if (kc + 1 < NCHUNK) {
            asm volatile("cp.async.wait_group 1;" ::: "memory");
        } else {
            asm volatile("cp.async.wait_group 0;" ::: "memory");
        }
        __syncthreads();

        const uint32_t base = sb + (kc % NSTG) * STAGE;
#pragma unroll
        for (int ks = 0; ks < 4; ++ks) {
            uint32_t ah[2][4];
#pragma unroll
            for (int mt = 0; mt < 2; ++mt) {
                uint32_t off = (uint32_t)((a_row + mt * 16) * STR +
                                          ks * 16 + a_col8) * 2;
                ldsm4(ah[mt], base + off);
            }
#pragma unroll
            for (int nb = 0; nb < 4; ++nb) {
                uint32_t bh[4];
                uint32_t off = (uint32_t)((b_row_base + nb * 16) * STR +
                                          ks * 16 + b_col8) * 2;
                ldsm4(bh, base + TILE + off);
#pragma unroll
                for (int mt = 0; mt < 2; ++mt) {
                    mma16816(acc[mt][2 * nb],     ah[mt], bh);
                    mma16816(acc[mt][2 * nb + 1], ah[mt], bh + 2);
                }
            }
        }
        __syncthreads();
    }

    if (tid < 128) { csum[tid] = 0.f; csq[tid] = 0.f; }
    __syncthreads();
#pragma unroll
    for (int nt = 0; nt < 8; ++nt) {
        int cl = warp_n * 64 + nt * 8 + 2 * (lane & 3);
        int c  = colBase + cl;
        float2 bv = *(const float2*)&bias[c];
        float s0 = 0.f, s1 = 0.f, q0 = 0.f, q1 = 0.f;
#pragma unroll
        for (int mt = 0; mt < 2; ++mt) {
            int r0 = rowBase + warp_m * 32 + mt * 16 + (lane >> 2);
            float2 v0 = {acc[mt][nt][0] + bv.x, acc[mt][nt][1] + bv.y};
            float2 v1 = {acc[mt][nt][2] + bv.x, acc[mt][nt][3] + bv.y};
            *(float2*)&C[(size_t)r0 * NCOLS + c]       = v0;
            *(float2*)&C[(size_t)(r0 + 8) * NCOLS + c] = v1;
            s0 += v0.x + v1.x;  s1 += v0.y + v1.y;
            q0 += v0.x * v0.x + v1.x * v1.x;
            q1 += v0.y * v0.y + v1.y * v1.y;
        }
        atomicAdd(&csum[cl], s0);     atomicAdd(&csum[cl + 1], s1);
        atomicAdd(&csq[cl],  q0);     atomicAdd(&csq[cl + 1],  q1);
    }
    __syncthreads();
    if (tid < 128) {
        atomicAdd(&stats[colBase + tid],         csum[tid]);
        atomicAdd(&stats[NCOLS + colBase + tid], csq[tid]);
    }
}

// ---- GEMM2: single fp16, TM=64, 2-stage, act fused, stats (R12, proven) ----
__global__ __launch_bounds__(256, 2)
void gemm2_k(const float* __restrict__ H1,
             const unsigned short* __restrict__ Bt,
             const float* __restrict__ g1, const float* __restrict__ be1,
             const float* __restrict__ bias, float* __restrict__ C,
             float* __restrict__ stats) {
    extern __shared__ char smem[];
    constexpr int KTOT = H1N, NCOLS = H2N;
    constexpr int STR    = 72;
    constexpr int TILE_A = 64 * STR * 2;
    constexpr int TILE_B = 128 * STR * 2;
    constexpr int STAGE  = TILE_A + TILE_B;
    constexpr int NCHUNK = KTOT / 64;            // 4
    __shared__ float sc[H1N], sh[H1N];
    __shared__ float csum[128], csq[128];

    const uint32_t sb = smem_u32(smem);
    const int tid = threadIdx.x;
    const int lane = tid & 31;
    const int wid = tid >> 5;
    const int warp_m = wid & 3;
    const int warp_n = wid >> 2;
    const int rowBase = blockIdx.x * 64;

    {
        float s  = g_stats1[tid];
        float sq = g_stats1[H1N + tid];
        float mean = s * (1.f / BATCH);
        float var  = sq * (1.f / BATCH) - mean * mean;
        float rstd = rsqrtf(var + BN_EPS);
        float scl  = g1[tid] * rstd;
        sc[tid] = scl;
        sh[tid] = be1[tid] - mean * scl;
    }
    __syncthreads();

    float acc[8][4];
#pragma unroll
    for (int j = 0; j < 8; ++j)
#pragma unroll
        for (int k = 0; k < 4; ++k) acc[j][k] = 0.f;

    const int a_row = warp_m * 16 + (lane & 15);
    const int a_col8 = (lane >> 4) << 3;
    const int b_row_base = warp_n * 64 + (lane & 7) + ((lane >> 4) << 3);
    const int b_col8 = ((lane >> 3) & 1) << 3;

    const int al_row = tid >> 2;
    const int al_seg = tid & 3;

    float4 ra[4];
    auto ldg_A = [&](int kc) {
#pragma unroll
        for (int p = 0; p < 4; ++p) {
            int kk = kc * 64 + (al_seg + p * 4) * 4;
            ra[p] = *(const float4*)&H1[(size_t)(rowBase + al_row) * KTOT + kk];
        }
    };
    auto store_A = [&](int kc) {
        const uint32_t base = (kc & 1) * STAGE;
#pragma unroll
        for (int p = 0; p < 4; ++p) {
            int kk = kc * 64 + (al_seg + p * 4) * 4;
            int cl = kk & (H1N - 1);
            float h0 = fmaxf(fmaf(ra[p].x, sc[cl + 0], sh[cl + 0]), 0.f);
            float h1 = fmaxf(fmaf(ra[p].y, sc[cl + 1], sh[cl + 1]), 0.f);
            float h2 = fmaxf(fmaf(ra[p].z, sc[cl + 2], sh[cl + 2]), 0.f);
            float h3 = fmaxf(fmaf(ra[p].w, sc[cl + 3], sh[cl + 3]), 0.f);
            __half2 a = __floats2half2_rn(h0, h1);
            __half2 b = __floats2half2_rn(h2, h3);
            uint32_t soff = base +
                (uint32_t)(al_row * STR + (al_seg + p * 4) * 4) * 2;
            *(uint32_t*)(smem + soff)     = *(uint32_t*)&a;
            *(uint32_t*)(smem + soff + 4) = *(uint32_t*)&b;
        }
    };
    auto load_B = [&](int kc) {
        const uint32_t base = sb + (kc & 1) * STAGE + TILE_A;
#pragma unroll
        for (int i = tid; i < 128 * 8; i += 256) {
            int row = i >> 3, seg = i & 7;
            uint32_t soff = (uint32_t)(row * STR + seg * 8) * 2;
            size_t gb = (size_t)row * KTOT + kc * 64 + seg * 8;
            cp16(base + soff, Bt + gb);
        }
        CP_COMMIT();
    };

    ldg_A(0);
    load_B(0);
    store_A(0);
    ldg_A(1);

    for (int kc = 0; kc < NCHUNK; ++kc) {
        if (kc + 1 < NCHUNK) {
            load_B(kc + 1);
            store_A(kc + 1);
            if (kc + 2 < NCHUNK) ldg_A(kc + 2);
            asm volatile("cp.async.wait_group 1;" ::: "memory");
        } else {
            asm volatile("cp.async.wait_group 0;" ::: "memory");
        }
        __syncthreads();

        const uint32_t baseA = sb + (kc & 1) * STAGE;
        const uint32_t baseB = baseA + TILE_A;
#pragma unroll
        for (int ks = 0; ks < 4; ++ks) {
            uint32_t ah[4];
            ldsm4(ah, baseA + (uint32_t)(a_row * STR + ks * 16 + a_col8) * 2);
#pragma unroll
            for (int nb = 0; nb < 4; ++nb) {
                uint32_t bh[4];
                uint32_t off = (uint32_t)((b_row_base + nb * 16) * STR +
                                          ks * 16 + b_col8) * 2;
                ldsm4(bh, baseB + off);
                mma16816(acc[2 * nb],     ah, bh);
                mma16816(acc[2 * nb + 1], ah, bh + 2);
            }
        }
        __syncthreads();
    }

    if (tid < 128) { csum[tid] = 0.f; csq[tid] = 0.f; }
    __syncthreads();
#pragma unroll
    for (int nt = 0; nt < 8; ++nt) {
        int cl = warp_n * 64 + nt * 8 + 2 * (lane & 3);
        float2 bv = *(const float2*)&bias[cl];
        int r0 = rowBase + warp_m * 16 + (lane >> 2);
        float2 v0 = {acc[nt][0] + bv.x, acc[nt][1] + bv.y};
        float2 v1 = {acc[nt][2] + bv.x, acc[nt][3] + bv.y};
        *(float2*)&C[(size_t)r0 * NCOLS + cl]       = v0;
        *(float2*)&C[(size_t)(r0 + 8) * NCOLS + cl] = v1;
        atomicAdd(&csum[cl],     v0.x + v1.x);
        atomicAdd(&csum[cl + 1], v0.y + v1.y);
        atomicAdd(&csq[cl],      v0.x * v0.x + v1.x * v1.x);
        atomicAdd(&csq[cl + 1],  v0.y * v0.y + v1.y * v1.y);
    }
    __syncthreads();
    if (tid < 128) {
        atomicAdd(&stats[tid],         csum[tid]);
        atomicAdd(&stats[NCOLS + tid], csq[tid]);
    }
}

// ---- final: out = fm + relu(BN(H2)) @ W3 + b3 ------------------------------
__global__ void final_k(const float* __restrict__ W3, const float* __restrict__ b3,
                        const float* __restrict__ g2, const float* __restrict__ be2,
                        float* __restrict__ out) {
    __shared__ float sc[H2N], sh[H2N], w3s[H2N];
    int tid = threadIdx.x;
    if (tid < H2N) {
        float s  = g_stats2[tid];
        float sq = g_stats2[H2N + tid];
        float mean = s * (1.f / BATCH);
        float var  = sq * (1.f / BATCH) - mean * mean;
        float rstd = rsqrtf(var + BN_EPS);
        float scl  = g2[tid] * rstd;
        sc[tid] = scl;
        sh[tid] = be2[tid] - mean * scl;
        w3s[tid] = W3[tid];
    }
    __syncthreads();
    int warp = tid >> 5, lane = tid & 31;
    int row = blockIdx.x * 8 + warp;
    float acc = 0.f;
#pragma unroll
    for (int j = 0; j < 4; ++j) {
        int c = lane + j * 32;
        float v = g_H2[(size_t)row * H2N + c];
        acc += fmaxf(fmaf(v, sc[c], sh[c]), 0.f) * w3s[c];
    }
#pragma unroll
    for (int o = 16; o; o >>= 1) acc += __shfl_xor_sync(0xffffffffu, acc, o);
    if (lane == 0) out[row] = g_fm[row] + acc + b3[0];
}

// ---------------------------------------------------------------------------
extern "C" void kernel_launch(void* const* d_in, const int* in_sizes, int n_in,
                              void* d_out, int out_size) {
    const int*   xc   = (const int*)  d_in[0];
    const float* lin  = (const float*)d_in[1];
    const float* lat  = (const float*)d_in[2];
    const float* W1   = (const float*)d_in[3];
    const float* b1   = (const float*)d_in[4];
    const float* g1   = (const float*)d_in[5];
    const float* be1  = (const float*)d_in[6];
    const float* W2   = (const float*)d_in[7];
    const float* b2   = (const float*)d_in[8];
    const float* g2   = (const float*)d_in[9];
    const float* be2  = (const float*)d_in[10];
    const float* W3   = (const float*)d_in[11];
    const float* b3   = (const float*)d_in[12];
    const float* bias = (const float*)d_in[13];
    float* out = (float*)d_out;

    unsigned short *pXh, *pW1, *pW2;
    float *pH1, *pH2, *pS1, *pS2;
    cudaGetSymbolAddress((void**)&pXh, g_Xh);
    cudaGetSymbolAddress((void**)&pW1, g_W1T);
    cudaGetSymbolAddress((void**)&pW2, g_W2T);
    cudaGetSymbolAddress((void**)&pH1, g_H1);
    cudaGetSymbolAddress((void**)&pH2, g_H2);
    cudaGetSymbolAddress((void**)&pS1, g_stats1);
    cudaGetSymbolAddress((void**)&pS2, g_stats2);

    constexpr int SMEM1 = 3 * 2 * 128 * 72 * 2;            // 110592 (3 stages)
    constexpr int SMEM2 = 2 * (64 + 128) * 72 * 2;         // 55296
    cudaFuncSetAttribute(gemm_fp16<DIN, H1N>,
                         cudaFuncAttributeMaxDynamicSharedMemorySize, SMEM1);
    cudaFuncSetAttribute(gemm2_k,
                         cudaFuncAttributeMaxDynamicSharedMemorySize, SMEM2);

    pre_k<<<2529, 256>>>(xc, lin, lat, bias, W1, W2);
    gemm_fp16<DIN, H1N><<<dim3(BATCH / 128, H1N / 128), 256, SMEM1>>>(
        pXh, pW1, b1, pH1, pS1);
    gemm2_k<<<BATCH / 64, 256, SMEM2>>>(pH1, pW2, g1, be1, b2, pH2, pS2);
    final_k<<<BATCH / 8, 256>>>(W3, b3, g2, be2, out);
}